// round 15
// baseline (speedup 1.0000x reference)
#include <cuda_runtime.h>
#include <cuda_fp16.h>
#include <cstdint>

#define OUTF 2048
#define INF  2048
#define NNZV 262144
#define NN   65536

#define NK16 (INF / 16)      // 128 k16 steps
#define NM16 (OUTF / 16)     // 128 m16 tiles
#define NN16 (NN / 16)       // 4096 n16 tiles

#define NSPLIT 4
#define NT_PER_SPLIT (NN16 / NSPLIT)              // 1024
#define UNITS_PER_SPLIT ((NT_PER_SPLIT / 2) * 8)  // 4096 units (2 nt x 16 kk each)

#define SM_STRIDE 132        // half2 per smem row (conflict-free fragment LDS)

// ---- device-global scratch ----
__device__ __align__(256) float g_W32[OUTF * INF];                 // 16 MB dense W accumulator
__device__ __align__(256) uint4 g_Wfrag[NM16 * NK16 * 32];         // 8 MB A-fragment-major W
__device__ __align__(256) uint4 g_Xf[(size_t)NN16 * NK16 * 32];    // 256 MB B-fragment-major x

// ---- helpers ----
__device__ __forceinline__ void mma16816(float* c, const uint4& a, uint32_t b0, uint32_t b1) {
    asm volatile(
        "mma.sync.aligned.m16n8k16.row.col.f32.f16.f16.f32 "
        "{%0,%1,%2,%3}, {%4,%5,%6,%7}, {%8,%9}, {%0,%1,%2,%3};"
        : "+f"(c[0]), "+f"(c[1]), "+f"(c[2]), "+f"(c[3])
        : "r"(a.x), "r"(a.y), "r"(a.z), "r"(a.w), "r"(b0), "r"(b1));
}
__device__ __forceinline__ uint32_t packh2(float lo, float hi) {
    __half2 h = __floats2half2_rn(lo, hi);
    return *reinterpret_cast<uint32_t*>(&h);
}
__device__ __forceinline__ uint32_t h2u(__half2 h) { return *reinterpret_cast<uint32_t*>(&h); }

// ---- coalesced smem-transpose pack of one unit: 2 n16-tiles x 16 kk (32 rows x 256 k) ----
__device__ __forceinline__ void pack_block(const float* __restrict__ x, __half2* sm,
                                           int nt0, int kc, int tid) {
    const int lr = tid >> 3;
    const int c8 = tid & 7;
#pragma unroll
    for (int h = 0; h < 2; h++) {
        const int row_l = h * 16 + lr;
        const float* src = x + (size_t)(nt0 * 16 + row_l) * INF + kc * 256;
#pragma unroll
        for (int rnd = 0; rnd < 8; rnd++) {
            const int c4 = c8 + rnd * 8;
            float4 v = *reinterpret_cast<const float4*>(src + c4 * 4);
            sm[row_l * SM_STRIDE + c4 * 2]     = __floats2half2_rn(v.x, v.y);
            sm[row_l * SM_STRIDE + c4 * 2 + 1] = __floats2half2_rn(v.z, v.w);
        }
    }
    __syncthreads();
    const int w = tid >> 5, l = tid & 31;
    const int nt_l = w >> 1;
    const int kkh = (w & 1) * 8;
    const int r0 = nt_l * 16 + (l >> 2);
    const int cb = l & 3;
#pragma unroll
    for (int i = 0; i < 8; i++) {
        const int kkl = kkh + i;
        uint4 f;
        f.x = h2u(sm[r0 * SM_STRIDE + kkl * 8 + cb]);
        f.y = h2u(sm[r0 * SM_STRIDE + kkl * 8 + cb + 4]);
        f.z = h2u(sm[(r0 + 8) * SM_STRIDE + kkl * 8 + cb]);
        f.w = h2u(sm[(r0 + 8) * SM_STRIDE + kkl * 8 + cb + 4]);
        g_Xf[((size_t)(nt0 + nt_l) * NK16 + (kc * 16 + kkl)) * 32 + l] = f;
    }
    __syncthreads();
}

// ---- prologue kernels ----
__global__ void zero_w_kernel() {
    int i = blockIdx.x * blockDim.x + threadIdx.x;
    reinterpret_cast<float4*>(g_W32)[i] = make_float4(0.f, 0.f, 0.f, 0.f);
}
__global__ void scatter_kernel(const float* __restrict__ vals, const int* __restrict__ rows,
                               const int* __restrict__ cols) {
    int i = blockIdx.x * blockDim.x + threadIdx.x;
    atomicAdd(&g_W32[rows[i] * INF + cols[i]], vals[i]);
}
__global__ void pack_w_kernel() {
    int t = blockIdx.x * blockDim.x + threadIdx.x;
    int lane = t & 31;
    int kk = (t >> 5) & (NK16 - 1);
    int T = t >> 12;
    int r0 = T * 16 + (lane >> 2);
    int kb = kk * 16 + (lane & 3) * 2;
    const float* W = g_W32;
    uint4 f;
    f.x = packh2(W[r0 * INF + kb],           W[r0 * INF + kb + 1]);
    f.y = packh2(W[(r0 + 8) * INF + kb],     W[(r0 + 8) * INF + kb + 1]);
    f.z = packh2(W[r0 * INF + kb + 8],       W[r0 * INF + kb + 9]);
    f.w = packh2(W[(r0 + 8) * INF + kb + 8], W[(r0 + 8) * INF + kb + 9]);
    g_Wfrag[t] = f;
}
__global__ void __launch_bounds__(128) pack_x0_kernel(const float* __restrict__ x) {
    __shared__ __half2 sm[32 * SM_STRIDE];
    const int u = blockIdx.x;
    pack_block(x, sm, (u >> 3) * 2, u & 7, threadIdx.x);
}

// ---- fused: every gemm CTA also packs 2 units of split s+1, injected at
// triple-iteration boundaries (a2/b2 dead there -> no register spill), with
// CTA-parity phase offset so co-resident CTAs don't burst simultaneously.
__global__ void __launch_bounds__(128, 2)
fused_kernel(const float* __restrict__ bias, float* __restrict__ out,
             const float* __restrict__ x, int s) {
    __shared__ __half2 sm[32 * SM_STRIDE];
    const int g = blockIdx.x;               // 0..2047
    const int bx = g & 15;                  // m tile (fast -> B L2 reuse)
    const int by = g >> 4;
    const int lid = threadIdx.x & 31;
    const int wid = threadIdx.x >> 5;
    const int wm = wid & 1;
    const int wn = wid >> 1;
    const int m0 = bx * 128;
    const int n_tile = s * (NN / 128 / NSPLIT) + by;
    const int n0 = n_tile * 128;

    const int m16b = bx * 8 + wm * 4;
    const int n16b = n_tile * 8 + wn * 4;

    const uint4* __restrict__ Ap = g_Wfrag + ((size_t)m16b * NK16) * 32 + lid;
    const uint4* __restrict__ Bp = g_Xf   + ((size_t)n16b * NK16) * 32 + lid;
    const size_t TS = (size_t)NK16 * 32;

    // pack assignment: units 2g and 2g+1 of split s+1
    const bool do_pack = (s + 1 < NSPLIT);
    const int base_nt = (s + 1) * NT_PER_SPLIT;
    const int u0 = g * 2, u1 = g * 2 + 1;
    const bool even = (g & 1) == 0;

    float acc[4][8][4];
#pragma unroll
    for (int mt = 0; mt < 4; mt++)
#pragma unroll
        for (int nt = 0; nt < 8; nt++)
#pragma unroll
            for (int e = 0; e < 4; e++) acc[mt][nt][e] = 0.f;

    uint4 a0[4], b0[4], a1[4], b1[4], a2[4], b2[4];
#pragma unroll
    for (int i = 0; i < 4; i++) { a0[i] = __ldg(Ap + i * TS);      b0[i] = __ldg(Bp + i * TS); }
#pragma unroll
    for (int i = 0; i < 4; i++) { a1[i] = __ldg(Ap + i * TS + 32); b1[i] = __ldg(Bp + i * TS + 32); }

    auto consume = [&](const uint4* a, const uint4* b) {
#pragma unroll
        for (int mt = 0; mt < 4; mt++)
#pragma unroll
            for (int j = 0; j < 4; j++) {
                mma16816(acc[mt][2 * j],     a[mt], b[j].x, b[j].y);
                mma16816(acc[mt][2 * j + 1], a[mt], b[j].z, b[j].w);
            }
    };

    const uint4* Ait = Ap;
    const uint4* Bit = Bp;
    // one branch-free triple (3 k16 steps); buffers rotate back to (a0,b0 | a1,b1)
    auto triples = [&](int n) {
#pragma unroll 1
        for (int it = 0; it < n; it++) {
#pragma unroll
            for (int i = 0; i < 4; i++) { a2[i] = __ldg(Ait + i * TS + 64); b2[i] = __ldg(Bit + i * TS + 64); }
            consume(a0, b0);
#pragma unroll
            for (int i = 0; i < 4; i++) { a0[i] = __ldg(Ait + i * TS + 96); b0[i] = __ldg(Bit + i * TS + 96); }
            consume(a1, b1);
#pragma unroll
            for (int i = 0; i < 4; i++) { a1[i] = __ldg(Ait + i * TS + 128); b1[i] = __ldg(Bit + i * TS + 128); }
            consume(a2, b2);
            Ait += 96; Bit += 96;
        }
    };

    // 42 triples total, pack bursts at boundaries (a2/b2 dead at these points)
    triples(10);
    if (do_pack && even)  pack_block(x, sm, base_nt + (u0 >> 3) * 2, u0 & 7, threadIdx.x);
    triples(7);
    if (do_pack && !even) pack_block(x, sm, base_nt + (u0 >> 3) * 2, u0 & 7, threadIdx.x);
    triples(7);
    if (do_pack && even)  pack_block(x, sm, base_nt + (u1 >> 3) * 2, u1 & 7, threadIdx.x);
    triples(7);
    if (do_pack && !even) pack_block(x, sm, base_nt + (u1 >> 3) * 2, u1 & 7, threadIdx.x);
    triples(11);
    consume(a0, b0);   // kk = 126
    consume(a1, b1);   // kk = 127

    // ---- epilogue ----
    const int q = lid >> 2;
    const int p2 = (lid & 3) << 1;
#pragma unroll
    for (int mt = 0; mt < 4; mt++) {
        const int o_lo = m0 + wm * 64 + mt * 16 + q;
        const float bv_lo = bias[o_lo];
        const float bv_hi = bias[o_lo + 8];
#pragma unroll
        for (int j = 0; j < 4; j++)
#pragma unroll
            for (int h = 0; h < 2; h++) {
                const int n = n0 + wn * 64 + j * 16 + h * 8 + p2;
                float* o0 = out + (size_t)n * OUTF;
                float* o1 = out + (size_t)(n + 1) * OUTF;
                const float* c = acc[mt][2 * j + h];
                o0[o_lo]     = c[0] + bv_lo;
                o1[o_lo]     = c[1] + bv_lo;
                o0[o_lo + 8] = c[2] + bv_hi;
                o1[o_lo + 8] = c[3] + bv_hi;
            }
    }
}

extern "C" void kernel_launch(void* const* d_in, const int* in_sizes, int n_in,
                              void* d_out, int out_size) {
    (void)in_sizes; (void)n_in; (void)out_size;
    const float* x      = (const float*)d_in[0];
    const float* values = (const float*)d_in[1];
    const float* bias   = (const float*)d_in[2];
    const int*   rows   = (const int*)d_in[3];
    const int*   cols   = (const int*)d_in[4];
    float* out = (float*)d_out;

    zero_w_kernel<<<(OUTF * INF / 4) / 256, 256>>>();
    scatter_kernel<<<NNZV / 256, 256>>>(values, rows, cols);
    pack_w_kernel<<<(NM16 * NK16 * 32) / 256, 256>>>();
    pack_x0_kernel<<<UNITS_PER_SPLIT, 128>>>(x);            // only exposed x-pack

    for (int s = 0; s < NSPLIT; s++) {
        fused_kernel<<<2048, 128>>>(bias, out, x, s);       // gemm(s) + in-CTA pack(s+1)
    }
}

// round 16
// speedup vs baseline: 1.0643x; 1.0643x over previous
#include <cuda_runtime.h>
#include <cuda_fp16.h>
#include <cstdint>

#define OUTF 2048
#define INF  2048
#define NNZV 262144
#define NN   65536

#define NK16 (INF / 16)      // 128 k16 steps
#define NM16 (OUTF / 16)     // 128 m16 tiles
#define NN16 (NN / 16)       // 4096 n16 tiles

#define SM_STRIDE 132        // half2 per smem row (conflict-free fragment LDS)

// Uneven n-splits (n128-tile counts): split 0 small -> minimal exposed pack.
// offsets: 0, 64, 192, 352; total 512 n128-tiles.
__constant__ int c_split_off[4] = {0, 64, 192, 352};
__constant__ int c_split_cnt[4] = {64, 128, 160, 160};

// ---- device-global scratch ----
__device__ __align__(256) float g_W32[OUTF * INF];                 // 16 MB dense W accumulator
__device__ __align__(256) uint4 g_Wfrag[NM16 * NK16 * 32];         // 8 MB A-fragment-major W
__device__ __align__(256) uint4 g_Xf[(size_t)NN16 * NK16 * 32];    // 256 MB B-fragment-major x

// ---- helpers ----
__device__ __forceinline__ void mma16816(float* c, const uint4& a, uint32_t b0, uint32_t b1) {
    asm volatile(
        "mma.sync.aligned.m16n8k16.row.col.f32.f16.f16.f32 "
        "{%0,%1,%2,%3}, {%4,%5,%6,%7}, {%8,%9}, {%0,%1,%2,%3};"
        : "+f"(c[0]), "+f"(c[1]), "+f"(c[2]), "+f"(c[3])
        : "r"(a.x), "r"(a.y), "r"(a.z), "r"(a.w), "r"(b0), "r"(b1));
}
__device__ __forceinline__ uint32_t packh2(float lo, float hi) {
    __half2 h = __floats2half2_rn(lo, hi);
    return *reinterpret_cast<uint32_t*>(&h);
}
__device__ __forceinline__ uint32_t h2u(__half2 h) { return *reinterpret_cast<uint32_t*>(&h); }

// ---- coalesced smem-transpose pack of one unit: 2 n16-tiles x 16 kk (32 rows x 256 k) ----
__device__ __forceinline__ void pack_block(const float* __restrict__ x, __half2* sm,
                                           int nt0, int kc, int tid) {
    const int lr = tid >> 3;
    const int c8 = tid & 7;
#pragma unroll
    for (int h = 0; h < 2; h++) {
        const int row_l = h * 16 + lr;
        const float* src = x + (size_t)(nt0 * 16 + row_l) * INF + kc * 256;
#pragma unroll
        for (int rnd = 0; rnd < 8; rnd++) {
            const int c4 = c8 + rnd * 8;
            float4 v = *reinterpret_cast<const float4*>(src + c4 * 4);
            sm[row_l * SM_STRIDE + c4 * 2]     = __floats2half2_rn(v.x, v.y);
            sm[row_l * SM_STRIDE + c4 * 2 + 1] = __floats2half2_rn(v.z, v.w);
        }
    }
    __syncthreads();
    const int w = tid >> 5, l = tid & 31;
    const int nt_l = w >> 1;
    const int kkh = (w & 1) * 8;
    const int r0 = nt_l * 16 + (l >> 2);
    const int cb = l & 3;
#pragma unroll
    for (int i = 0; i < 8; i++) {
        const int kkl = kkh + i;
        uint4 f;
        f.x = h2u(sm[r0 * SM_STRIDE + kkl * 8 + cb]);
        f.y = h2u(sm[r0 * SM_STRIDE + kkl * 8 + cb + 4]);
        f.z = h2u(sm[(r0 + 8) * SM_STRIDE + kkl * 8 + cb]);
        f.w = h2u(sm[(r0 + 8) * SM_STRIDE + kkl * 8 + cb + 4]);
        g_Xf[((size_t)(nt0 + nt_l) * NK16 + (kc * 16 + kkl)) * 32 + l] = f;
    }
    __syncthreads();
}
// A-fragment pack of one element index t (per-thread)
__device__ __forceinline__ void pack_w_one(int t) {
    int lane = t & 31;
    int kk = (t >> 5) & (NK16 - 1);
    int T = t >> 12;
    int r0 = T * 16 + (lane >> 2);
    int kb = kk * 16 + (lane & 3) * 2;
    const float* W = g_W32;
    uint4 f;
    f.x = packh2(W[r0 * INF + kb],           W[r0 * INF + kb + 1]);
    f.y = packh2(W[(r0 + 8) * INF + kb],     W[(r0 + 8) * INF + kb + 1]);
    f.z = packh2(W[r0 * INF + kb + 8],       W[r0 * INF + kb + 9]);
    f.w = packh2(W[(r0 + 8) * INF + kb + 8], W[(r0 + 8) * INF + kb + 9]);
    g_Wfrag[t] = f;
}

// ---- prologue kernels ----
__global__ void zero_w_kernel() {
    int i = blockIdx.x * blockDim.x + threadIdx.x;
    reinterpret_cast<float4*>(g_W32)[i] = make_float4(0.f, 0.f, 0.f, 0.f);
}
__global__ void scatter_kernel(const float* __restrict__ vals, const int* __restrict__ rows,
                               const int* __restrict__ cols) {
    int i = blockIdx.x * blockDim.x + threadIdx.x;
    atomicAdd(&g_W32[rows[i] * INF + cols[i]], vals[i]);
}
// merged: pack_w (bid < 4096, 128 thr -> 524288 elements) + pack of x split 0
// (bid-4096 in [0, 32*c0), one unit each). Both depend only on scatter.
__global__ void __launch_bounds__(128) packs_kernel(const float* __restrict__ x) {
    __shared__ __half2 sm[32 * SM_STRIDE];
    const int bid = blockIdx.x;
    if (bid < 4096) {
        pack_w_one(bid * 128 + threadIdx.x);
    } else {
        const int u = bid - 4096;             // split 0 unit
        pack_block(x, sm, (u >> 3) * 2, u & 7, threadIdx.x);
    }
}

// ---- fused: gemm(split s) + pack CTAs for split s+1, proportionally interleaved ----
// grid = G + P; pack iff floor((bid+1)P/T) > floor(bid*P/T). Pack CTA p does 8 units.
__global__ void __launch_bounds__(128, 2)
fused_kernel(const float* __restrict__ bias, float* __restrict__ out,
             const float* __restrict__ x, int s, int G, int P) {
    __shared__ __half2 sm[32 * SM_STRIDE];
    const int bid = blockIdx.x;
    const int T = G + P;
    const int packs_before = (int)(((long long)bid * P) / T);
    const bool is_pack = ((long long)(bid + 1) * P) / T != packs_before;

    if (is_pack) {
        const int p = packs_before;
        const int base_nt16 = c_split_off[s + 1] * 8;
#pragma unroll 1
        for (int j = 0; j < 8; j++) {
            const int u = p * 8 + j;
            pack_block(x, sm, base_nt16 + (u >> 3) * 2, u & 7, threadIdx.x);
        }
        return;
    }

    // ---- gemm role ----
    const int g = bid - packs_before;       // 0..G-1
    const int bx = g & 15;                  // m tile (fast -> B L2 reuse)
    const int by = g >> 4;                  // n128 tile within split
    const int lid = threadIdx.x & 31;
    const int wid = threadIdx.x >> 5;
    const int wm = wid & 1;
    const int wn = wid >> 1;
    const int m0 = bx * 128;
    const int n_tile = c_split_off[s] + by;
    const int n0 = n_tile * 128;

    const int m16b = bx * 8 + wm * 4;
    const int n16b = n_tile * 8 + wn * 4;

    const uint4* __restrict__ Ap = g_Wfrag + ((size_t)m16b * NK16) * 32 + lid;
    const uint4* __restrict__ Bp = g_Xf   + ((size_t)n16b * NK16) * 32 + lid;
    const size_t TS = (size_t)NK16 * 32;

    float acc[4][8][4];
#pragma unroll
    for (int mt = 0; mt < 4; mt++)
#pragma unroll
        for (int nt = 0; nt < 8; nt++)
#pragma unroll
            for (int e = 0; e < 4; e++) acc[mt][nt][e] = 0.f;

    uint4 a0[4], b0[4], a1[4], b1[4], a2[4], b2[4];
#pragma unroll
    for (int i = 0; i < 4; i++) { a0[i] = __ldg(Ap + i * TS);      b0[i] = __ldg(Bp + i * TS); }
#pragma unroll
    for (int i = 0; i < 4; i++) { a1[i] = __ldg(Ap + i * TS + 32); b1[i] = __ldg(Bp + i * TS + 32); }

    auto consume = [&](const uint4* a, const uint4* b) {
#pragma unroll
        for (int mt = 0; mt < 4; mt++)
#pragma unroll
            for (int j = 0; j < 4; j++) {
                mma16816(acc[mt][2 * j],     a[mt], b[j].x, b[j].y);
                mma16816(acc[mt][2 * j + 1], a[mt], b[j].z, b[j].w);
            }
    };

    const uint4* Ait = Ap;
    const uint4* Bit = Bp;
#pragma unroll 1
    for (int it = 0; it < 42; it++) {
#pragma unroll
        for (int i = 0; i < 4; i++) { a2[i] = __ldg(Ait + i * TS + 64); b2[i] = __ldg(Bit + i * TS + 64); }
        consume(a0, b0);
#pragma unroll
        for (int i = 0; i < 4; i++) { a0[i] = __ldg(Ait + i * TS + 96); b0[i] = __ldg(Bit + i * TS + 96); }
        consume(a1, b1);
#pragma unroll
        for (int i = 0; i < 4; i++) { a1[i] = __ldg(Ait + i * TS + 128); b1[i] = __ldg(Bit + i * TS + 128); }
        consume(a2, b2);
        Ait += 96; Bit += 96;
    }
    consume(a0, b0);   // kk = 126
    consume(a1, b1);   // kk = 127

    // ---- epilogue ----
    const int q = lid >> 2;
    const int p2 = (lid & 3) << 1;
#pragma unroll
    for (int mt = 0; mt < 4; mt++) {
        const int o_lo = m0 + wm * 64 + mt * 16 + q;
        const float bv_lo = bias[o_lo];
        const float bv_hi = bias[o_lo + 8];
#pragma unroll
        for (int j = 0; j < 4; j++)
#pragma unroll
            for (int h = 0; h < 2; h++) {
                const int n = n0 + wn * 64 + j * 16 + h * 8 + p2;
                float* o0 = out + (size_t)n * OUTF;
                float* o1 = out + (size_t)(n + 1) * OUTF;
                const float* c = acc[mt][2 * j + h];
                o0[o_lo]     = c[0] + bv_lo;
                o1[o_lo]     = c[1] + bv_lo;
                o0[o_lo + 8] = c[2] + bv_hi;
                o1[o_lo + 8] = c[3] + bv_hi;
            }
    }
}

extern "C" void kernel_launch(void* const* d_in, const int* in_sizes, int n_in,
                              void* d_out, int out_size) {
    (void)in_sizes; (void)n_in; (void)out_size;
    const float* x      = (const float*)d_in[0];
    const float* values = (const float*)d_in[1];
    const float* bias   = (const float*)d_in[2];
    const int*   rows   = (const int*)d_in[3];
    const int*   cols   = (const int*)d_in[4];
    float* out = (float*)d_out;

    static const int h_off[4] = {0, 64, 192, 352};
    static const int h_cnt[4] = {64, 128, 160, 160};

    zero_w_kernel<<<(OUTF * INF / 4) / 256, 256>>>();
    scatter_kernel<<<NNZV / 256, 256>>>(values, rows, cols);
    // merged pack_w + pack_x(split 0): 4096 + 32*64 = 6144 CTAs
    packs_kernel<<<4096 + 32 * h_cnt[0], 128>>>(x);

    for (int s = 0; s < 4; s++) {
        const int G = 16 * h_cnt[s];
        const int P = (s + 1 < 4) ? 4 * h_cnt[s + 1] : 0;
        fused_kernel<<<G + P, 128>>>(bias, out, x, s, G, P);
    }
}

// round 17
// speedup vs baseline: 1.0787x; 1.0135x over previous
#include <cuda_runtime.h>
#include <cuda_fp16.h>
#include <cstdint>

#define OUTF 2048
#define INF  2048
#define NNZV 262144
#define NN   65536

#define NK16 (INF / 16)      // 128 k16 steps
#define NM16 (OUTF / 16)     // 128 m16 tiles
#define NN16 (NN / 16)       // 4096 n16 tiles

#define SM_STRIDE 132        // half2 per smem row (conflict-free fragment LDS)

// ---- device-global scratch ----
__device__ __align__(256) float g_W32[OUTF * INF];                 // 16 MB dense W accumulator
__device__ __align__(256) uint4 g_Wfrag[NM16 * NK16 * 32];         // 8 MB A-fragment-major W
__device__ __align__(256) uint4 g_Xf[(size_t)NN16 * NK16 * 32];    // 256 MB B-fragment-major x

// ---- helpers ----
__device__ __forceinline__ void mma16816(float* c, const uint4& a, uint32_t b0, uint32_t b1) {
    asm volatile(
        "mma.sync.aligned.m16n8k16.row.col.f32.f16.f16.f32 "
        "{%0,%1,%2,%3}, {%4,%5,%6,%7}, {%8,%9}, {%0,%1,%2,%3};"
        : "+f"(c[0]), "+f"(c[1]), "+f"(c[2]), "+f"(c[3])
        : "r"(a.x), "r"(a.y), "r"(a.z), "r"(a.w), "r"(b0), "r"(b1));
}
__device__ __forceinline__ uint32_t packh2(float lo, float hi) {
    __half2 h = __floats2half2_rn(lo, hi);
    return *reinterpret_cast<uint32_t*>(&h);
}
__device__ __forceinline__ uint32_t h2u(__half2 h) { return *reinterpret_cast<uint32_t*>(&h); }

// ---- prologue kernels ----
__global__ void zero_w_kernel() {
    int i = blockIdx.x * blockDim.x + threadIdx.x;
    reinterpret_cast<float4*>(g_W32)[i] = make_float4(0.f, 0.f, 0.f, 0.f);
}
__global__ void scatter_kernel(const float* __restrict__ vals, const int* __restrict__ rows,
                               const int* __restrict__ cols) {
    int i = blockIdx.x * blockDim.x + threadIdx.x;
    atomicAdd(&g_W32[rows[i] * INF + cols[i]], vals[i]);
}

// A-fragment pack of element index t
__device__ __forceinline__ void pack_w_one(int t) {
    int lane = t & 31;
    int kk = (t >> 5) & (NK16 - 1);
    int T = t >> 12;
    int r0 = T * 16 + (lane >> 2);
    int kb = kk * 16 + (lane & 3) * 2;
    const float* W = g_W32;
    uint4 f;
    f.x = packh2(W[r0 * INF + kb],           W[r0 * INF + kb + 1]);
    f.y = packh2(W[(r0 + 8) * INF + kb],     W[(r0 + 8) * INF + kb + 1]);
    f.z = packh2(W[r0 * INF + kb + 8],       W[r0 * INF + kb + 9]);
    f.w = packh2(W[(r0 + 8) * INF + kb + 8], W[(r0 + 8) * INF + kb + 9]);
    g_Wfrag[t] = f;
}

// ---- merged pack kernel: 256 threads/CTA ----
// bid < 2048             : W-pack, one element per thread (524288 total)
// bid in [2048, 2048+8192): x-pack, one 64-row x 256-col unit per CTA
//   (4 n16-tiles x 16 kk) via coalesced LDG.128 -> cvt -> smem transpose
//   (stride-132 rows, store-phase LDS hits 32 distinct banks) -> STG.128.
__global__ void __launch_bounds__(256) packs_kernel(const float* __restrict__ x) {
    __shared__ __half2 sm[64 * SM_STRIDE];   // 33.8 KB
    const int bid = blockIdx.x;
    const int tid = threadIdx.x;

    if (bid < 2048) {
        pack_w_one(bid * 256 + tid);
        return;
    }
    const int u = bid - 2048;               // 0..8191
    const int nt0 = (u >> 3) * 4;           // first n16 tile (4 per unit)
    const int kc = u & 7;                   // 256-k chunk

    // load phase: 64 rows x 64 float4, coalesced (warp = 4 rows x 128B)
    const int lr = tid >> 3;                // 0..31
    const int c8 = tid & 7;
#pragma unroll
    for (int h = 0; h < 2; h++) {
        const int row_l = h * 32 + lr;      // 0..63
        const float* src = x + (size_t)(nt0 * 16 + row_l) * INF + kc * 256;
#pragma unroll
        for (int rnd = 0; rnd < 8; rnd++) {
            const int c4 = c8 + rnd * 8;    // 0..63
            float4 v = *reinterpret_cast<const float4*>(src + c4 * 4);
            sm[row_l * SM_STRIDE + c4 * 2]     = __floats2half2_rn(v.x, v.y);
            sm[row_l * SM_STRIDE + c4 * 2 + 1] = __floats2half2_rn(v.z, v.w);
        }
    }
    __syncthreads();

    // store phase: 8 warps; warp w -> nt_l = w/2, kk-half = (w&1)*8
    const int w = tid >> 5, l = tid & 31;
    const int nt_l = w >> 1;                // 0..3
    const int kkh = (w & 1) * 8;
    const int r0 = nt_l * 16 + (l >> 2);
    const int cb = l & 3;
#pragma unroll
    for (int i = 0; i < 8; i++) {
        const int kkl = kkh + i;            // 0..15
        uint4 f;
        f.x = h2u(sm[r0 * SM_STRIDE + kkl * 8 + cb]);
        f.y = h2u(sm[r0 * SM_STRIDE + kkl * 8 + cb + 4]);
        f.z = h2u(sm[(r0 + 8) * SM_STRIDE + kkl * 8 + cb]);
        f.w = h2u(sm[(r0 + 8) * SM_STRIDE + kkl * 8 + cb + 4]);
        g_Xf[((size_t)(nt0 + nt_l) * NK16 + (kc * 16 + kkl)) * 32 + l] = f;
    }
}

// ---- GEMM: out[n, o] = sum_k W[o,k] * x[n,k] + bias[o] ----
// Single launch, 8192 CTAs (m-fastest for B L2 reuse), 4 warps/CTA,
// warp tile 64x64, register-only 3-buffer pipeline at prefetch distance 2,
// branch-free steady loop (R12 structure).
__global__ void __launch_bounds__(128, 2)
gemm_kernel(const float* __restrict__ bias, float* __restrict__ out) {
    const int g = blockIdx.x;               // 0..8191
    const int bx = g & 15;                  // m tile (fast)
    const int n_tile = g >> 4;              // 0..511
    const int lid = threadIdx.x & 31;
    const int wid = threadIdx.x >> 5;
    const int wm = wid & 1;
    const int wn = wid >> 1;
    const int m0 = bx * 128;
    const int n0 = n_tile * 128;

    const int m16b = bx * 8 + wm * 4;
    const int n16b = n_tile * 8 + wn * 4;

    const uint4* __restrict__ Ap = g_Wfrag + ((size_t)m16b * NK16) * 32 + lid;
    const uint4* __restrict__ Bp = g_Xf   + ((size_t)n16b * NK16) * 32 + lid;
    const size_t TS = (size_t)NK16 * 32;

    float acc[4][8][4];
#pragma unroll
    for (int mt = 0; mt < 4; mt++)
#pragma unroll
        for (int nt = 0; nt < 8; nt++)
#pragma unroll
            for (int e = 0; e < 4; e++) acc[mt][nt][e] = 0.f;

    uint4 a0[4], b0[4], a1[4], b1[4], a2[4], b2[4];
#pragma unroll
    for (int i = 0; i < 4; i++) { a0[i] = __ldg(Ap + i * TS);      b0[i] = __ldg(Bp + i * TS); }
#pragma unroll
    for (int i = 0; i < 4; i++) { a1[i] = __ldg(Ap + i * TS + 32); b1[i] = __ldg(Bp + i * TS + 32); }

    auto consume = [&](const uint4* a, const uint4* b) {
#pragma unroll
        for (int mt = 0; mt < 4; mt++)
#pragma unroll
            for (int j = 0; j < 4; j++) {
                mma16816(acc[mt][2 * j],     a[mt], b[j].x, b[j].y);
                mma16816(acc[mt][2 * j + 1], a[mt], b[j].z, b[j].w);
            }
    };

    const uint4* Ait = Ap;
    const uint4* Bit = Bp;
#pragma unroll 1
    for (int it = 0; it < 42; it++) {
#pragma unroll
        for (int i = 0; i < 4; i++) { a2[i] = __ldg(Ait + i * TS + 64); b2[i] = __ldg(Bit + i * TS + 64); }
        consume(a0, b0);
#pragma unroll
        for (int i = 0; i < 4; i++) { a0[i] = __ldg(Ait + i * TS + 96); b0[i] = __ldg(Bit + i * TS + 96); }
        consume(a1, b1);
#pragma unroll
        for (int i = 0; i < 4; i++) { a1[i] = __ldg(Ait + i * TS + 128); b1[i] = __ldg(Bit + i * TS + 128); }
        consume(a2, b2);
        Ait += 96; Bit += 96;
    }
    consume(a0, b0);   // kk = 126
    consume(a1, b1);   // kk = 127

    // ---- epilogue: out[n, o] = acc + bias[o] ----
    const int q = lid >> 2;
    const int p2 = (lid & 3) << 1;
#pragma unroll
    for (int mt = 0; mt < 4; mt++) {
        const int o_lo = m0 + wm * 64 + mt * 16 + q;
        const float bv_lo = bias[o_lo];
        const float bv_hi = bias[o_lo + 8];
#pragma unroll
        for (int j = 0; j < 4; j++)
#pragma unroll
            for (int h = 0; h < 2; h++) {
                const int n = n0 + wn * 64 + j * 16 + h * 8 + p2;
                float* o0 = out + (size_t)n * OUTF;
                float* o1 = out + (size_t)(n + 1) * OUTF;
                const float* c = acc[mt][2 * j + h];
                o0[o_lo]     = c[0] + bv_lo;
                o1[o_lo]     = c[1] + bv_lo;
                o0[o_lo + 8] = c[2] + bv_hi;
                o1[o_lo + 8] = c[3] + bv_hi;
            }
    }
}

extern "C" void kernel_launch(void* const* d_in, const int* in_sizes, int n_in,
                              void* d_out, int out_size) {
    (void)in_sizes; (void)n_in; (void)out_size;
    const float* x      = (const float*)d_in[0];
    const float* values = (const float*)d_in[1];
    const float* bias   = (const float*)d_in[2];
    const int*   rows   = (const int*)d_in[3];
    const int*   cols   = (const int*)d_in[4];
    float* out = (float*)d_out;

    zero_w_kernel<<<(OUTF * INF / 4) / 256, 256>>>();
    scatter_kernel<<<NNZV / 256, 256>>>(values, rows, cols);
    packs_kernel<<<2048 + 8192, 256>>>(x);      // W-pack + full x-pack, serial
    gemm_kernel<<<8192, 128>>>(bias, out);      // single clean GEMM launch
}